// round 9
// baseline (speedup 1.0000x reference)
#include <cuda_runtime.h>

// ---------------------------------------------------------------------------
// EngramModule fused forward.
// Stage 1: per-slot projection tables. 128x64 tiles, 128 threads, 8x8
//          microtile, FFMA2 core. Two k-chunks of 32 (4 syncs/block),
//          conflict-free transpose stores.
// Stage 2: warp-per-(16-token run, stream), one-token software pipeline
//          (unchanged from R8 best: 58.5us).
// ---------------------------------------------------------------------------

#define Bq    8
#define Tq    4096
#define CHq   512
#define R_TOK 16
#define CHUNKS (Tq / R_TOK)   // 256

__device__ float g_Vtab[16384 * 128];   // 8 MB
__device__ float g_Ktab[16384 * 512];   // 32 MB

__device__ __forceinline__ unsigned long long pk2(float lo, float hi) {
    unsigned long long r;
    asm("mov.b64 %0, {%1, %2};" : "=l"(r) : "f"(lo), "f"(hi));
    return r;
}
__device__ __forceinline__ void upk2(float& lo, float& hi, unsigned long long v) {
    asm("mov.b64 {%0, %1}, %2;" : "=f"(lo), "=f"(hi) : "l"(v));
}
__device__ __forceinline__ void ffma2(unsigned long long& d,
                                      unsigned long long a,
                                      unsigned long long b) {
    asm("fma.rn.f32x2 %0, %1, %2, %0;" : "+l"(d) : "l"(a), "l"(b));
}

// ---------------------------------------------------------------------------
// Stage 1: 4 group-GEMMs of (4096 x 64) @ (64 x 640), fp32, FFMA2 core.
// Block = 128 rows x 64 cols, 128 threads, 8x8 microtile, 2 k-chunks of 32.
// ---------------------------------------------------------------------------
__global__ void __launch_bounds__(128) precompute_kernel(
    const float* __restrict__ emb,      // (16384, 64)
    const float* __restrict__ valW,     // (128, 256)
    const float* __restrict__ keyW,     // (512, 256)
    const float* __restrict__ valb,     // (128)
    const float* __restrict__ keyb)     // (512)
{
    __shared__ __align__(16) float As[32][132];   // [e][row]
    __shared__ __align__(16) float Bs[32][68];    // [e][col]

    const int tid  = threadIdx.x;
    const int nblk = blockIdx.x;   // 0..9  (64-col tile)
    const int mblk = blockIdx.y;   // 0..31 (128-row tile within group)
    const int g    = blockIdx.z;   // 0..3

    const int row0 = (tid >> 3) << 3;   // 0..120
    const int col0 = (tid & 7) << 3;    // 0..56

    unsigned long long acc2[8][4];
#pragma unroll
    for (int i = 0; i < 8; i++)
#pragma unroll
        for (int j = 0; j < 4; j++) acc2[i][j] = 0ull;

    const int gcol0 = nblk << 6;
    const float* abase = emb + (size_t)((g << 12) + (mblk << 7)) * 64;
    const float* bbase = ((gcol0 < 128) ? (valW + (size_t)gcol0 * 256)
                                        : (keyW + (size_t)(gcol0 - 128) * 256))
                         + g * 64;

    const int myrow = tid;         // A loader: thread owns one of 128 rows
    const int bcol  = tid & 63;    // B loader: thread owns one of 64 cols
    const int bhalf = tid >> 6;    // covers e-halves 0..15 / 16..31

#pragma unroll
    for (int kc = 0; kc < 2; kc++) {
        // A: thread loads its row's 32 e's (8 float4), scatter-stores
        // transposed. STS addr = (e)*132 + myrow -> lane-consecutive,
        // conflict-free.
#pragma unroll
        for (int u = 0; u < 8; u++) {
            float4 av = *(const float4*)(abase + myrow * 64 + kc * 32 + u * 4);
            As[u * 4 + 0][myrow] = av.x;
            As[u * 4 + 1][myrow] = av.y;
            As[u * 4 + 2][myrow] = av.z;
            As[u * 4 + 3][myrow] = av.w;
        }
        // B: thread owns col bcol, e-half bhalf (4 float4), conflict-free STS.
#pragma unroll
        for (int u = 0; u < 4; u++) {
            const int j4 = bhalf * 16 + u * 4;
            float4 bv = *(const float4*)(bbase + bcol * 256 + kc * 32 + j4);
            Bs[j4 + 0][bcol] = bv.x;
            Bs[j4 + 1][bcol] = bv.y;
            Bs[j4 + 2][bcol] = bv.z;
            Bs[j4 + 3][bcol] = bv.w;
        }
        __syncthreads();
#pragma unroll
        for (int e = 0; e < 32; e++) {
            float4 a0 = *(const float4*)&As[e][row0];
            float4 a1 = *(const float4*)&As[e][row0 + 4];
            float4 b0 = *(const float4*)&Bs[e][col0];
            float4 b1 = *(const float4*)&Bs[e][col0 + 4];
            unsigned long long bj[4] = {pk2(b0.x, b0.y), pk2(b0.z, b0.w),
                                        pk2(b1.x, b1.y), pk2(b1.z, b1.w)};
            float ar[8] = {a0.x, a0.y, a0.z, a0.w, a1.x, a1.y, a1.z, a1.w};
#pragma unroll
            for (int i = 0; i < 8; i++) {
                unsigned long long ai = pk2(ar[i], ar[i]);
#pragma unroll
                for (int j = 0; j < 4; j++)
                    ffma2(acc2[i][j], ai, bj[j]);
            }
        }
        __syncthreads();
    }

    const int slot0 = (g << 12) + (mblk << 7) + row0;
    const int gcol  = gcol0 + col0;
    const float* bias = (gcol < 128) ? (valb + gcol) : (keyb + gcol - 128);
    float4 bia = *(const float4*)(bias);
    float4 bib = *(const float4*)(bias + 4);

#pragma unroll
    for (int i = 0; i < 8; i++) {
        float r[8];
        upk2(r[0], r[1], acc2[i][0]);
        upk2(r[2], r[3], acc2[i][1]);
        upk2(r[4], r[5], acc2[i][2]);
        upk2(r[6], r[7], acc2[i][3]);
        float4 o0 = make_float4(r[0] + 0.25f * bia.x, r[1] + 0.25f * bia.y,
                                r[2] + 0.25f * bia.z, r[3] + 0.25f * bia.w);
        float4 o1 = make_float4(r[4] + 0.25f * bib.x, r[5] + 0.25f * bib.y,
                                r[6] + 0.25f * bib.z, r[7] + 0.25f * bib.w);
        float* dst = (gcol < 128)
            ? g_Vtab + (size_t)(slot0 + i) * 128 + gcol
            : g_Ktab + (size_t)(slot0 + i) * 512 + (gcol - 128);
        *(float4*)(dst)     = o0;
        *(float4*)(dst + 4) = o1;
    }
}

// ---------------------------------------------------------------------------
// Stage 2 main kernel (unchanged R8). Block = 128 threads = 4 stream-warps
// of one 16-token chunk. Prefetched Tok(t+1) issued before compute(t).
// ---------------------------------------------------------------------------
struct Tok {
    float4 k0, k1, k2, k3;
    float4 v0, v1, v2, v3;
    float4 q;
};

__global__ void __launch_bounds__(128, 5) engram_main_kernel(
    const float* __restrict__ x,        // (B,T,4,128)
    const int*   __restrict__ ids,      // (B,T)
    const int*   __restrict__ mult,     // (2,2,3)
    const float* __restrict__ wq,       // (4,128)
    const float* __restrict__ wk,       // (4,128)
    const float* __restrict__ convw,    // (512,4)
    const float* __restrict__ convn,    // (4,128)
    float*       __restrict__ out)      // (B,T,4,128)
{
    const int stream = threadIdx.x >> 5;
    const int lane   = threadIdx.x & 31;
    const int b      = blockIdx.x >> 8;       // CHUNKS = 256
    const int chunk  = blockIdx.x & 255;
    const int t0     = chunk * R_TOK;

    const int c = stream * 128 + lane * 4;
    const int d = lane * 4;

    const float4 wq4  = *(const float4*)(wq + c);
    const float4 wk4  = *(const float4*)(wk + c);
    const float4 wqk4 = make_float4(wq4.x * wk4.x, wq4.y * wk4.y,
                                    wq4.z * wk4.z, wq4.w * wk4.w);
    const float4 cvn4 = *(const float4*)(convn + c);
    const float4 cwA  = *(const float4*)(convw + (c + 0) * 4);
    const float4 cwB  = *(const float4*)(convw + (c + 1) * 4);
    const float4 cwC  = *(const float4*)(convw + (c + 2) * 4);
    const float4 cwD  = *(const float4*)(convw + (c + 3) * 4);

    const int m00 = mult[0],  m01 = mult[1];
    const int m10 = mult[3],  m11 = mult[4];
    const int m20 = mult[6],  m21 = mult[7],  m22 = mult[8];
    const int m30 = mult[9],  m31 = mult[10], m32 = mult[11];

    const float inv128     = 0.0078125f;
    const float eps        = 1.1920929e-7f;
    const float invsqrt128 = 0.08838834764831845f;

    const int    idBase = b * Tq;
    const float* xBase  = x   + (size_t)idBase * CHq + c;
    float*       oBase  = out + (size_t)idBase * CHq + c;

    float4 h1 = make_float4(0.f, 0.f, 0.f, 0.f);
    float4 h2 = h1;
    float4 h3 = h1;

    auto gather = [&](Tok& T, int ia, int ib, int ic, int t) {
        const int h0i = (((ib * m00) ^ (ic * m01)) & 4095);
        const int h1i = (((ib * m10) ^ (ic * m11)) & 4095) + 4096;
        const int h2i = (((ia * m20) ^ (ib * m21) ^ (ic * m22)) & 4095) + 8192;
        const int h3i = (((ia * m30) ^ (ib * m31) ^ (ic * m32)) & 4095) + 12288;
        T.k0 = __ldg((const float4*)(g_Ktab + (size_t)h0i * 512 + c));
        T.k1 = __ldg((const float4*)(g_Ktab + (size_t)h1i * 512 + c));
        T.k2 = __ldg((const float4*)(g_Ktab + (size_t)h2i * 512 + c));
        T.k3 = __ldg((const float4*)(g_Ktab + (size_t)h3i * 512 + c));
        T.v0 = __ldg((const float4*)(g_Vtab + (size_t)h0i * 128 + d));
        T.v1 = __ldg((const float4*)(g_Vtab + (size_t)h1i * 128 + d));
        T.v2 = __ldg((const float4*)(g_Vtab + (size_t)h2i * 128 + d));
        T.v3 = __ldg((const float4*)(g_Vtab + (size_t)h3i * 128 + d));
        T.q  = *(const float4*)(xBase + (size_t)t * CHq);
    };

    auto compute = [&](const Tok& T, int t, bool store) {
        float4 kr, vb;
        kr.x = (T.k0.x + T.k1.x) + (T.k2.x + T.k3.x);
        kr.y = (T.k0.y + T.k1.y) + (T.k2.y + T.k3.y);
        kr.z = (T.k0.z + T.k1.z) + (T.k2.z + T.k3.z);
        kr.w = (T.k0.w + T.k1.w) + (T.k2.w + T.k3.w);
        vb.x = (T.v0.x + T.v1.x) + (T.v2.x + T.v3.x);
        vb.y = (T.v0.y + T.v1.y) + (T.v2.y + T.v3.y);
        vb.z = (T.v0.z + T.v1.z) + (T.v2.z + T.v3.z);
        vb.w = (T.v0.w + T.v1.w) + (T.v2.w + T.v3.w);

        float p0 = T.q.x * T.q.x + T.q.y * T.q.y + T.q.z * T.q.z + T.q.w * T.q.w;
        float p1 = kr.x * kr.x + kr.y * kr.y + kr.z * kr.z + kr.w * kr.w;
        float p2 = T.q.x * kr.x * wqk4.x + T.q.y * kr.y * wqk4.y
                 + T.q.z * kr.z * wqk4.z + T.q.w * kr.w * wqk4.w;
        float p3 = vb.x * vb.x + vb.y * vb.y + vb.z * vb.z + vb.w * vb.w;

        const bool lo = (lane < 16);
        float ea = __shfl_xor_sync(0xffffffffu, p0, 16);
        float eb = __shfl_xor_sync(0xffffffffu, p2, 16);
        float aa = lo ? (p0 + ea) : (p2 + eb);
        float ec = __shfl_xor_sync(0xffffffffu, p1, 16);
        float ed = __shfl_xor_sync(0xffffffffu, p3, 16);
        float bb = lo ? (p1 + ec) : (p3 + ed);
#pragma unroll
        for (int off = 8; off; off >>= 1) {
            aa += __shfl_xor_sync(0xffffffffu, aa, off);
            bb += __shfl_xor_sync(0xffffffffu, bb, off);
        }
        const float a2 = __shfl_xor_sync(0xffffffffu, aa, 16);
        const float b2 = __shfl_xor_sync(0xffffffffu, bb, 16);
        const float sq  = lo ? aa : a2;
        const float sk  = lo ? bb : b2;
        const float sqk = lo ? a2 : aa;
        const float svb = lo ? b2 : bb;

        const float rsq   = rsqrtf(sq * inv128 + eps);
        const float rsk   = rsqrtf(sk * inv128 + eps);
        const float score = sqk * rsq * rsk * invsqrt128;
        const float gate  = __fdividef(1.f, 1.f + __expf(-score));
        const float rr    = rsqrtf(gate * gate * svb * inv128 + eps) * gate;

        float4 xn;
        xn.x = vb.x * rr * cvn4.x;  xn.y = vb.y * rr * cvn4.y;
        xn.z = vb.z * rr * cvn4.z;  xn.w = vb.w * rr * cvn4.w;

        if (store) {
            float4 y;
            y.x = cwA.x * h3.x + cwA.y * h2.x + cwA.z * h1.x + cwA.w * xn.x;
            y.y = cwB.x * h3.y + cwB.y * h2.y + cwB.z * h1.y + cwB.w * xn.y;
            y.z = cwC.x * h3.z + cwC.y * h2.z + cwC.z * h1.z + cwC.w * xn.z;
            y.w = cwD.x * h3.w + cwD.y * h2.w + cwD.z * h1.w + cwD.w * xn.w;
            y.x = __fdividef(y.x, 1.f + __expf(-y.x));
            y.y = __fdividef(y.y, 1.f + __expf(-y.y));
            y.z = __fdividef(y.z, 1.f + __expf(-y.z));
            y.w = __fdividef(y.w, 1.f + __expf(-y.w));
            float4 o;
            o.x = vb.x * gate + y.x;  o.y = vb.y * gate + y.y;
            o.z = vb.z * gate + y.z;  o.w = vb.w * gate + y.w;
            *(float4*)(oBase + (size_t)t * CHq) = o;
        }
        h3 = h2; h2 = h1; h1 = xn;
    };

    int ia = (t0 - 5 >= 0) ? __ldg(ids + idBase + t0 - 5) : 0;
    int ib = (t0 - 4 >= 0) ? __ldg(ids + idBase + t0 - 4) : 0;

    // ---- halo prologue: tokens t0-3 .. t0-1 (no store, unpipelined) ----
#pragma unroll
    for (int tt = -3; tt < 0; tt++) {
        const int t  = t0 + tt;
        const int ic = (t >= 0) ? __ldg(ids + idBase + t) : 0;
        if (t >= 0) {
            Tok P;
            gather(P, ia, ib, ic, t);
            compute(P, t, false);
        }
        ia = ib; ib = ic;
    }

    // ---- pipelined main loop: tokens t0 .. t0+R_TOK-1 ----
    int ic = __ldg(ids + idBase + t0);
    Tok cur;
    gather(cur, ia, ib, ic, t0);

    for (int tt = 0; tt < R_TOK; tt++) {
        const int t = t0 + tt;
        Tok nxt;
        int in_ = ic;
        if (tt + 1 < R_TOK) {
            in_ = __ldg(ids + idBase + t + 1);
            gather(nxt, ib, ic, in_, t + 1);   // issue before compute(cur)
        }
        compute(cur, t, true);
        ia = ib; ib = ic; ic = in_;
        cur = nxt;
    }
}

// ---------------------------------------------------------------------------
extern "C" void kernel_launch(void* const* d_in, const int* in_sizes, int n_in,
                              void* d_out, int out_size)
{
    const float* x          = (const float*)d_in[0];
    const int*   input_ids  = (const int*)  d_in[1];
    const int*   multipliers= (const int*)  d_in[2];
    const float* embedding  = (const float*)d_in[3];
    const float* val_W      = (const float*)d_in[4];
    const float* val_b      = (const float*)d_in[5];
    const float* key_W      = (const float*)d_in[6];
    const float* key_b      = (const float*)d_in[7];
    const float* normq_w    = (const float*)d_in[8];
    const float* normk_w    = (const float*)d_in[9];
    const float* conv_w     = (const float*)d_in[10];
    const float* convnorm_w = (const float*)d_in[11];
    float* out = (float*)d_out;

    dim3 gp(10, 32, 4);
    precompute_kernel<<<gp, 128>>>(embedding, val_W, key_W, val_b, key_b);

    engram_main_kernel<<<Bq * CHUNKS, 128>>>(
        x, input_ids, multipliers,
        normq_w, normk_w, conv_w, convnorm_w, out);
}

// round 10
// speedup vs baseline: 1.1288x; 1.1288x over previous
#include <cuda_runtime.h>
#include <cuda_bf16.h>

// ---------------------------------------------------------------------------
// EngramModule fused forward.
// Stage 1: per-slot projection tables (R8 GEMM: 128x64 tiles, 128 thr,
//          k-chunks of 16, FFMA2). K table stored bf16, V table fp32.
// Stage 2: warp-per-(16-token run, stream), one-token software pipeline.
//          K gathers are bf16 (half the L1 wavefronts).
// ---------------------------------------------------------------------------

#define Bq    8
#define Tq    4096
#define CHq   512
#define R_TOK 16
#define CHUNKS (Tq / R_TOK)   // 256

__device__ float         g_Vtab[16384 * 128];   // 8 MB fp32
__device__ __nv_bfloat16 g_Ktab[16384 * 512];   // 16 MB bf16

__device__ __forceinline__ unsigned long long pk2(float lo, float hi) {
    unsigned long long r;
    asm("mov.b64 %0, {%1, %2};" : "=l"(r) : "f"(lo), "f"(hi));
    return r;
}
__device__ __forceinline__ void upk2(float& lo, float& hi, unsigned long long v) {
    asm("mov.b64 {%0, %1}, %2;" : "=f"(lo), "=f"(hi) : "l"(v));
}
__device__ __forceinline__ void ffma2(unsigned long long& d,
                                      unsigned long long a,
                                      unsigned long long b) {
    asm("fma.rn.f32x2 %0, %1, %2, %0;" : "+l"(d) : "l"(a), "l"(b));
}

// ---------------------------------------------------------------------------
// Stage 1: 4 group-GEMMs of (4096 x 64) @ (64 x 640), fp32 compute.
// Block = 128 rows x 64 cols, 128 threads, 8x8 microtile, k-chunks of 16.
// (R8 loader: coalesced LDG, transposed STS.)
// ---------------------------------------------------------------------------
__global__ void __launch_bounds__(128) precompute_kernel(
    const float* __restrict__ emb,      // (16384, 64)
    const float* __restrict__ valW,     // (128, 256)
    const float* __restrict__ keyW,     // (512, 256)
    const float* __restrict__ valb,     // (128)
    const float* __restrict__ keyb)     // (512)
{
    __shared__ __align__(16) float As[16][132];
    __shared__ __align__(16) float Bs[16][68];

    const int tid  = threadIdx.x;
    const int nblk = blockIdx.x;   // 0..9  (64-col tile)
    const int mblk = blockIdx.y;   // 0..31 (128-row tile within group)
    const int g    = blockIdx.z;   // 0..3

    const int row0 = (tid >> 3) << 3;   // 0..120
    const int col0 = (tid & 7) << 3;    // 0..56

    unsigned long long acc2[8][4];
#pragma unroll
    for (int i = 0; i < 8; i++)
#pragma unroll
        for (int j = 0; j < 4; j++) acc2[i][j] = 0ull;

    const int gcol0 = nblk << 6;
    const float* abase = emb + (size_t)((g << 12) + (mblk << 7)) * 64;
    const float* bbase = ((gcol0 < 128) ? (valW + (size_t)gcol0 * 256)
                                        : (keyW + (size_t)(gcol0 - 128) * 256))
                         + g * 64;

#pragma unroll
    for (int kc = 0; kc < 4; kc++) {
        // A: 128 rows x 16 e  -> 4 float4/thread (coalesced)
#pragma unroll
        for (int u = 0; u < 4; u++) {
            const int f   = tid + (u << 7);     // 0..511
            const int row = f >> 2;             // 0..127
            const int j   = (f & 3) << 2;       // e-offset
            float4 av = *(const float4*)(abase + row * 64 + kc * 16 + j);
            As[j + 0][row] = av.x; As[j + 1][row] = av.y;
            As[j + 2][row] = av.z; As[j + 3][row] = av.w;
        }
        // B: 64 cols x 16 e -> 2 float4/thread (coalesced)
#pragma unroll
        for (int u = 0; u < 2; u++) {
            const int f   = tid + (u << 7);     // 0..255
            const int row = f >> 2;             // 0..63
            const int j   = (f & 3) << 2;
            float4 bv = *(const float4*)(bbase + row * 256 + kc * 16 + j);
            Bs[j + 0][row] = bv.x; Bs[j + 1][row] = bv.y;
            Bs[j + 2][row] = bv.z; Bs[j + 3][row] = bv.w;
        }
        __syncthreads();
#pragma unroll
        for (int e = 0; e < 16; e++) {
            float4 a0 = *(const float4*)&As[e][row0];
            float4 a1 = *(const float4*)&As[e][row0 + 4];
            float4 b0 = *(const float4*)&Bs[e][col0];
            float4 b1 = *(const float4*)&Bs[e][col0 + 4];
            unsigned long long bj[4] = {pk2(b0.x, b0.y), pk2(b0.z, b0.w),
                                        pk2(b1.x, b1.y), pk2(b1.z, b1.w)};
            float ar[8] = {a0.x, a0.y, a0.z, a0.w, a1.x, a1.y, a1.z, a1.w};
#pragma unroll
            for (int i = 0; i < 8; i++) {
                unsigned long long ai = pk2(ar[i], ar[i]);
#pragma unroll
                for (int j = 0; j < 4; j++)
                    ffma2(acc2[i][j], ai, bj[j]);
            }
        }
        __syncthreads();
    }

    const int slot0 = (g << 12) + (mblk << 7) + row0;
    const int gcol  = gcol0 + col0;
    const float* bias = (gcol < 128) ? (valb + gcol) : (keyb + gcol - 128);
    float4 bia = *(const float4*)(bias);
    float4 bib = *(const float4*)(bias + 4);

#pragma unroll
    for (int i = 0; i < 8; i++) {
        float r[8];
        upk2(r[0], r[1], acc2[i][0]);
        upk2(r[2], r[3], acc2[i][1]);
        upk2(r[4], r[5], acc2[i][2]);
        upk2(r[6], r[7], acc2[i][3]);
        float4 o0 = make_float4(r[0] + 0.25f * bia.x, r[1] + 0.25f * bia.y,
                                r[2] + 0.25f * bia.z, r[3] + 0.25f * bia.w);
        float4 o1 = make_float4(r[4] + 0.25f * bib.x, r[5] + 0.25f * bib.y,
                                r[6] + 0.25f * bib.z, r[7] + 0.25f * bib.w);
        if (gcol < 128) {
            float* dst = g_Vtab + (size_t)(slot0 + i) * 128 + gcol;
            *(float4*)(dst)     = o0;
            *(float4*)(dst + 4) = o1;
        } else {
            __nv_bfloat162 p0 = __float22bfloat162_rn(make_float2(o0.x, o0.y));
            __nv_bfloat162 p1 = __float22bfloat162_rn(make_float2(o0.z, o0.w));
            __nv_bfloat162 p2 = __float22bfloat162_rn(make_float2(o1.x, o1.y));
            __nv_bfloat162 p3 = __float22bfloat162_rn(make_float2(o1.z, o1.w));
            uint4 w;
            w.x = *(unsigned int*)&p0;  w.y = *(unsigned int*)&p1;
            w.z = *(unsigned int*)&p2;  w.w = *(unsigned int*)&p3;
            *(uint4*)(g_Ktab + (size_t)(slot0 + i) * 512 + (gcol - 128)) = w;
        }
    }
}

// ---------------------------------------------------------------------------
// Stage 2 main kernel. Block = 128 threads = 4 stream-warps of one 16-token
// chunk. Prefetched Tok(t+1) issued before compute(t); K rows gathered bf16.
// ---------------------------------------------------------------------------
struct Tok {
    uint2  K0, K1, K2, K3;      // 4 bf16 values per row slice
    float4 v0, v1, v2, v3;
    float4 q;
};

__device__ __forceinline__ float4 bf4(uint2 u) {
    float2 a = __bfloat1622float2(*reinterpret_cast<const __nv_bfloat162*>(&u.x));
    float2 b = __bfloat1622float2(*reinterpret_cast<const __nv_bfloat162*>(&u.y));
    return make_float4(a.x, a.y, b.x, b.y);
}

__global__ void __launch_bounds__(128, 5) engram_main_kernel(
    const float* __restrict__ x,        // (B,T,4,128)
    const int*   __restrict__ ids,      // (B,T)
    const int*   __restrict__ mult,     // (2,2,3)
    const float* __restrict__ wq,       // (4,128)
    const float* __restrict__ wk,       // (4,128)
    const float* __restrict__ convw,    // (512,4)
    const float* __restrict__ convn,    // (4,128)
    float*       __restrict__ out)      // (B,T,4,128)
{
    const int stream = threadIdx.x >> 5;
    const int lane   = threadIdx.x & 31;
    const int b      = blockIdx.x >> 8;       // CHUNKS = 256
    const int chunk  = blockIdx.x & 255;
    const int t0     = chunk * R_TOK;

    const int c = stream * 128 + lane * 4;
    const int d = lane * 4;

    const float4 wq4  = *(const float4*)(wq + c);
    const float4 wk4  = *(const float4*)(wk + c);
    const float4 wqk4 = make_float4(wq4.x * wk4.x, wq4.y * wk4.y,
                                    wq4.z * wk4.z, wq4.w * wk4.w);
    const float4 cvn4 = *(const float4*)(convn + c);
    const float4 cwA  = *(const float4*)(convw + (c + 0) * 4);
    const float4 cwB  = *(const float4*)(convw + (c + 1) * 4);
    const float4 cwC  = *(const float4*)(convw + (c + 2) * 4);
    const float4 cwD  = *(const float4*)(convw + (c + 3) * 4);

    const int m00 = mult[0],  m01 = mult[1];
    const int m10 = mult[3],  m11 = mult[4];
    const int m20 = mult[6],  m21 = mult[7],  m22 = mult[8];
    const int m30 = mult[9],  m31 = mult[10], m32 = mult[11];

    const float inv128     = 0.0078125f;
    const float eps        = 1.1920929e-7f;
    const float invsqrt128 = 0.08838834764831845f;

    const int    idBase = b * Tq;
    const float* xBase  = x   + (size_t)idBase * CHq + c;
    float*       oBase  = out + (size_t)idBase * CHq + c;

    float4 h1 = make_float4(0.f, 0.f, 0.f, 0.f);
    float4 h2 = h1;
    float4 h3 = h1;

    auto gather = [&](Tok& T, int ia, int ib, int ic, int t) {
        const int h0i = (((ib * m00) ^ (ic * m01)) & 4095);
        const int h1i = (((ib * m10) ^ (ic * m11)) & 4095) + 4096;
        const int h2i = (((ia * m20) ^ (ib * m21) ^ (ic * m22)) & 4095) + 8192;
        const int h3i = (((ia * m30) ^ (ib * m31) ^ (ic * m32)) & 4095) + 12288;
        T.K0 = __ldg((const uint2*)(g_Ktab + (size_t)h0i * 512 + c));
        T.K1 = __ldg((const uint2*)(g_Ktab + (size_t)h1i * 512 + c));
        T.K2 = __ldg((const uint2*)(g_Ktab + (size_t)h2i * 512 + c));
        T.K3 = __ldg((const uint2*)(g_Ktab + (size_t)h3i * 512 + c));
        T.v0 = __ldg((const float4*)(g_Vtab + (size_t)h0i * 128 + d));
        T.v1 = __ldg((const float4*)(g_Vtab + (size_t)h1i * 128 + d));
        T.v2 = __ldg((const float4*)(g_Vtab + (size_t)h2i * 128 + d));
        T.v3 = __ldg((const float4*)(g_Vtab + (size_t)h3i * 128 + d));
        T.q  = *(const float4*)(xBase + (size_t)t * CHq);
    };

    auto compute = [&](const Tok& T, int t, bool store) {
        const float4 k0 = bf4(T.K0);
        const float4 k1 = bf4(T.K1);
        const float4 k2 = bf4(T.K2);
        const float4 k3 = bf4(T.K3);
        float4 kr, vb;
        kr.x = (k0.x + k1.x) + (k2.x + k3.x);
        kr.y = (k0.y + k1.y) + (k2.y + k3.y);
        kr.z = (k0.z + k1.z) + (k2.z + k3.z);
        kr.w = (k0.w + k1.w) + (k2.w + k3.w);
        vb.x = (T.v0.x + T.v1.x) + (T.v2.x + T.v3.x);
        vb.y = (T.v0.y + T.v1.y) + (T.v2.y + T.v3.y);
        vb.z = (T.v0.z + T.v1.z) + (T.v2.z + T.v3.z);
        vb.w = (T.v0.w + T.v1.w) + (T.v2.w + T.v3.w);

        float p0 = T.q.x * T.q.x + T.q.y * T.q.y + T.q.z * T.q.z + T.q.w * T.q.w;
        float p1 = kr.x * kr.x + kr.y * kr.y + kr.z * kr.z + kr.w * kr.w;
        float p2 = T.q.x * kr.x * wqk4.x + T.q.y * kr.y * wqk4.y
                 + T.q.z * kr.z * wqk4.z + T.q.w * kr.w * wqk4.w;
        float p3 = vb.x * vb.x + vb.y * vb.y + vb.z * vb.z + vb.w * vb.w;

        const bool lo = (lane < 16);
        float ea = __shfl_xor_sync(0xffffffffu, p0, 16);
        float eb = __shfl_xor_sync(0xffffffffu, p2, 16);
        float aa = lo ? (p0 + ea) : (p2 + eb);
        float ec = __shfl_xor_sync(0xffffffffu, p1, 16);
        float ed = __shfl_xor_sync(0xffffffffu, p3, 16);
        float bb = lo ? (p1 + ec) : (p3 + ed);
#pragma unroll
        for (int off = 8; off; off >>= 1) {
            aa += __shfl_xor_sync(0xffffffffu, aa, off);
            bb += __shfl_xor_sync(0xffffffffu, bb, off);
        }
        const float a2 = __shfl_xor_sync(0xffffffffu, aa, 16);
        const float b2 = __shfl_xor_sync(0xffffffffu, bb, 16);
        const float sq  = lo ? aa : a2;
        const float sk  = lo ? bb : b2;
        const float sqk = lo ? a2 : aa;
        const float svb = lo ? b2 : bb;

        const float rsq   = rsqrtf(sq * inv128 + eps);
        const float rsk   = rsqrtf(sk * inv128 + eps);
        const float score = sqk * rsq * rsk * invsqrt128;
        const float gate  = __fdividef(1.f, 1.f + __expf(-score));
        const float rr    = rsqrtf(gate * gate * svb * inv128 + eps) * gate;

        float4 xn;
        xn.x = vb.x * rr * cvn4.x;  xn.y = vb.y * rr * cvn4.y;
        xn.z = vb.z * rr * cvn4.z;  xn.w = vb.w * rr * cvn4.w;

        if (store) {
            float4 y;
            y.x = cwA.x * h3.x + cwA.y * h2.x + cwA.z * h1.x + cwA.w * xn.x;
            y.y = cwB.x * h3.y + cwB.y * h2.y + cwB.z * h1.y + cwB.w * xn.y;
            y.z = cwC.x * h3.z + cwC.y * h2.z + cwC.z * h1.z + cwC.w * xn.z;
            y.w = cwD.x * h3.w + cwD.y * h2.w + cwD.z * h1.w + cwD.w * xn.w;
            y.x = __fdividef(y.x, 1.f + __expf(-y.x));
            y.y = __fdividef(y.y, 1.f + __expf(-y.y));
            y.z = __fdividef(y.z, 1.f + __expf(-y.z));
            y.w = __fdividef(y.w, 1.f + __expf(-y.w));
            float4 o;
            o.x = vb.x * gate + y.x;  o.y = vb.y * gate + y.y;
            o.z = vb.z * gate + y.z;  o.w = vb.w * gate + y.w;
            *(float4*)(oBase + (size_t)t * CHq) = o;
        }
        h3 = h2; h2 = h1; h1 = xn;
    };

    int ia = (t0 - 5 >= 0) ? __ldg(ids + idBase + t0 - 5) : 0;
    int ib = (t0 - 4 >= 0) ? __ldg(ids + idBase + t0 - 4) : 0;

    // ---- halo prologue: tokens t0-3 .. t0-1 (no store, unpipelined) ----
#pragma unroll
    for (int tt = -3; tt < 0; tt++) {
        const int t  = t0 + tt;
        const int ic = (t >= 0) ? __ldg(ids + idBase + t) : 0;
        if (t >= 0) {
            Tok P;
            gather(P, ia, ib, ic, t);
            compute(P, t, false);
        }
        ia = ib; ib = ic;
    }

    // ---- pipelined main loop: tokens t0 .. t0+R_TOK-1 ----
    int ic = __ldg(ids + idBase + t0);
    Tok cur;
    gather(cur, ia, ib, ic, t0);

    for (int tt = 0; tt < R_TOK; tt++) {
        const int t = t0 + tt;
        Tok nxt;
        int in_ = ic;
        if (tt + 1 < R_TOK) {
            in_ = __ldg(ids + idBase + t + 1);
            gather(nxt, ib, ic, in_, t + 1);   // issue before compute(cur)
        }
        compute(cur, t, true);
        ia = ib; ib = ic; ic = in_;
        cur = nxt;
    }
}

// ---------------------------------------------------------------------------
extern "C" void kernel_launch(void* const* d_in, const int* in_sizes, int n_in,
                              void* d_out, int out_size)
{
    const float* x          = (const float*)d_in[0];
    const int*   input_ids  = (const int*)  d_in[1];
    const int*   multipliers= (const int*)  d_in[2];
    const float* embedding  = (const float*)d_in[3];
    const float* val_W      = (const float*)d_in[4];
    const float* val_b      = (const float*)d_in[5];
    const float* key_W      = (const float*)d_in[6];
    const float* key_b      = (const float*)d_in[7];
    const float* normq_w    = (const float*)d_in[8];
    const float* normk_w    = (const float*)d_in[9];
    const float* conv_w     = (const float*)d_in[10];
    const float* convnorm_w = (const float*)d_in[11];
    float* out = (float*)d_out;

    dim3 gp(10, 32, 4);
    precompute_kernel<<<gp, 128>>>(embedding, val_W, key_W, val_b, key_b);

    engram_main_kernel<<<Bq * CHUNKS, 128>>>(
        x, input_ids, multipliers,
        normq_w, normk_w, conv_w, convnorm_w, out);
}

// round 11
// speedup vs baseline: 1.2795x; 1.1335x over previous
#include <cuda_runtime.h>
#include <cuda_bf16.h>

// ---------------------------------------------------------------------------
// EngramModule fused forward.
// Stage 1a: V table (16384x128, fp32) via FFMA2 GEMM (exact).
// Stage 1b: K table (16384x512, bf16) via warp-level bf16 MMA (HMMA),
//           fp32 accumulate, ldmatrix operand loads.
// Stage 2:  main fused kernel (unchanged R10 best: 56.9us).
// ---------------------------------------------------------------------------

#define Bq    8
#define Tq    4096
#define CHq   512
#define R_TOK 16
#define CHUNKS (Tq / R_TOK)   // 256

__device__ float         g_Vtab[16384 * 128];   // 8 MB fp32
__device__ __nv_bfloat16 g_Ktab[16384 * 512];   // 16 MB bf16

__device__ __forceinline__ unsigned long long pk2(float lo, float hi) {
    unsigned long long r;
    asm("mov.b64 %0, {%1, %2};" : "=l"(r) : "f"(lo), "f"(hi));
    return r;
}
__device__ __forceinline__ void upk2(float& lo, float& hi, unsigned long long v) {
    asm("mov.b64 {%0, %1}, %2;" : "=f"(lo), "=f"(hi) : "l"(v));
}
__device__ __forceinline__ void ffma2(unsigned long long& d,
                                      unsigned long long a,
                                      unsigned long long b) {
    asm("fma.rn.f32x2 %0, %1, %2, %0;" : "+l"(d) : "l"(a), "l"(b));
}

// ---------------------------------------------------------------------------
// Stage 1a: V table, fp32 FFMA2 GEMM (R8/R10 kernel, grid.x = 2 -> V cols only)
// ---------------------------------------------------------------------------
__global__ void __launch_bounds__(128) precompute_v_kernel(
    const float* __restrict__ emb,      // (16384, 64)
    const float* __restrict__ valW,     // (128, 256)
    const float* __restrict__ valb)     // (128)
{
    __shared__ __align__(16) float As[16][132];
    __shared__ __align__(16) float Bs[16][68];

    const int tid  = threadIdx.x;
    const int nblk = blockIdx.x;   // 0..1  (64-col tile within V)
    const int mblk = blockIdx.y;   // 0..31
    const int g    = blockIdx.z;   // 0..3

    const int row0 = (tid >> 3) << 3;
    const int col0 = (tid & 7) << 3;

    unsigned long long acc2[8][4];
#pragma unroll
    for (int i = 0; i < 8; i++)
#pragma unroll
        for (int j = 0; j < 4; j++) acc2[i][j] = 0ull;

    const int gcol0 = nblk << 6;
    const float* abase = emb + (size_t)((g << 12) + (mblk << 7)) * 64;
    const float* bbase = valW + (size_t)gcol0 * 256 + g * 64;

#pragma unroll
    for (int kc = 0; kc < 4; kc++) {
#pragma unroll
        for (int u = 0; u < 4; u++) {
            const int f   = tid + (u << 7);
            const int row = f >> 2;
            const int j   = (f & 3) << 2;
            float4 av = *(const float4*)(abase + row * 64 + kc * 16 + j);
            As[j + 0][row] = av.x; As[j + 1][row] = av.y;
            As[j + 2][row] = av.z; As[j + 3][row] = av.w;
        }
#pragma unroll
        for (int u = 0; u < 2; u++) {
            const int f   = tid + (u << 7);
            const int row = f >> 2;
            const int j   = (f & 3) << 2;
            float4 bv = *(const float4*)(bbase + row * 256 + kc * 16 + j);
            Bs[j + 0][row] = bv.x; Bs[j + 1][row] = bv.y;
            Bs[j + 2][row] = bv.z; Bs[j + 3][row] = bv.w;
        }
        __syncthreads();
#pragma unroll
        for (int e = 0; e < 16; e++) {
            float4 a0 = *(const float4*)&As[e][row0];
            float4 a1 = *(const float4*)&As[e][row0 + 4];
            float4 b0 = *(const float4*)&Bs[e][col0];
            float4 b1 = *(const float4*)&Bs[e][col0 + 4];
            unsigned long long bj[4] = {pk2(b0.x, b0.y), pk2(b0.z, b0.w),
                                        pk2(b1.x, b1.y), pk2(b1.z, b1.w)};
            float ar[8] = {a0.x, a0.y, a0.z, a0.w, a1.x, a1.y, a1.z, a1.w};
#pragma unroll
            for (int i = 0; i < 8; i++) {
                unsigned long long ai = pk2(ar[i], ar[i]);
#pragma unroll
                for (int j = 0; j < 4; j++)
                    ffma2(acc2[i][j], ai, bj[j]);
            }
        }
        __syncthreads();
    }

    const int slot0 = (g << 12) + (mblk << 7) + row0;
    const int gcol  = gcol0 + col0;
    float4 bia = *(const float4*)(valb + gcol);
    float4 bib = *(const float4*)(valb + gcol + 4);

#pragma unroll
    for (int i = 0; i < 8; i++) {
        float r[8];
        upk2(r[0], r[1], acc2[i][0]);
        upk2(r[2], r[3], acc2[i][1]);
        upk2(r[4], r[5], acc2[i][2]);
        upk2(r[6], r[7], acc2[i][3]);
        float* dst = g_Vtab + (size_t)(slot0 + i) * 128 + gcol;
        *(float4*)(dst)     = make_float4(r[0] + 0.25f * bia.x, r[1] + 0.25f * bia.y,
                                          r[2] + 0.25f * bia.z, r[3] + 0.25f * bia.w);
        *(float4*)(dst + 4) = make_float4(r[4] + 0.25f * bib.x, r[5] + 0.25f * bib.y,
                                          r[6] + 0.25f * bib.z, r[7] + 0.25f * bib.w);
    }
}

// ---------------------------------------------------------------------------
// Stage 1b: K table via bf16 warp-MMA.
// Block = 256 thr = 8 warps, tile 128 slots x 64 K-cols, K=64 (4 k-steps).
// Warp (wm 0..3, wn 0..1) computes a 32x32 subtile = 2m x 4n x 4k MMAs.
// Smem rows padded to 72 bf16 (144 B) -> ldmatrix conflict-free.
// ---------------------------------------------------------------------------
__global__ void __launch_bounds__(256) ktab_mma_kernel(
    const float* __restrict__ emb,      // (16384, 64)
    const float* __restrict__ keyW,     // (512, 256)
    const float* __restrict__ keyb)     // (512)
{
    __shared__ __align__(16) __nv_bfloat16 Asm[128 * 72];
    __shared__ __align__(16) __nv_bfloat16 Bsm[64 * 72];

    const int tid  = threadIdx.x;
    const int nblk = blockIdx.x;   // 0..7  -> K cols [nblk*64, +64)
    const int mblk = blockIdx.y;   // 0..31
    const int g    = blockIdx.z;   // 0..3

    // ---- stage A (emb tile, 128x64 fp32 -> bf16) ----
    const float* abase = emb + (size_t)((g << 12) + (mblk << 7)) * 64;
#pragma unroll
    for (int u = 0; u < 8; u++) {
        const int idx = tid + (u << 8);     // 0..2047
        const int row = idx >> 4;
        const int c4  = idx & 15;
        float4 v = *(const float4*)(abase + row * 64 + c4 * 4);
        __nv_bfloat162 p0 = __float22bfloat162_rn(make_float2(v.x, v.y));
        __nv_bfloat162 p1 = __float22bfloat162_rn(make_float2(v.z, v.w));
        uint2 w;
        w.x = *(unsigned int*)&p0;  w.y = *(unsigned int*)&p1;
        *(uint2*)(Asm + row * 72 + c4 * 4) = w;
    }
    // ---- stage B (keyW tile [col][k], 64x64 fp32 -> bf16) ----
    const float* bbase = keyW + (size_t)(nblk << 6) * 256 + g * 64;
#pragma unroll
    for (int u = 0; u < 4; u++) {
        const int idx = tid + (u << 8);     // 0..1023
        const int row = idx >> 4;           // 0..63
        const int c4  = idx & 15;
        float4 v = *(const float4*)(bbase + row * 256 + c4 * 4);
        __nv_bfloat162 p0 = __float22bfloat162_rn(make_float2(v.x, v.y));
        __nv_bfloat162 p1 = __float22bfloat162_rn(make_float2(v.z, v.w));
        uint2 w;
        w.x = *(unsigned int*)&p0;  w.y = *(unsigned int*)&p1;
        *(uint2*)(Bsm + row * 72 + c4 * 4) = w;
    }
    __syncthreads();

    const int warp = tid >> 5;
    const int lane = tid & 31;
    const int wm = warp & 3;        // 0..3 -> 32-row strip
    const int wn = warp >> 2;       // 0..1 -> 32-col strip

    float acc[2][4][4];
#pragma unroll
    for (int mi = 0; mi < 2; mi++)
#pragma unroll
        for (int ni = 0; ni < 4; ni++)
#pragma unroll
            for (int r = 0; r < 4; r++) acc[mi][ni][r] = 0.f;

    const unsigned int asmb = (unsigned int)__cvta_generic_to_shared(Asm);
    const unsigned int bsmb = (unsigned int)__cvta_generic_to_shared(Bsm);
    const int arow  = lane & 15;
    const int ahalf = lane >> 4;
    const int brow  = lane & 7;
    const int bhalf = (lane >> 3) & 1;

#pragma unroll
    for (int ks = 0; ks < 4; ks++) {
        unsigned int af[2][4];
#pragma unroll
        for (int mi = 0; mi < 2; mi++) {
            unsigned int addr = asmb
                + (unsigned int)((wm * 32 + mi * 16 + arow) * 144)
                + ks * 32 + ahalf * 16;
            asm volatile(
                "ldmatrix.sync.aligned.m8n8.x4.shared.b16 {%0,%1,%2,%3}, [%4];"
                : "=r"(af[mi][0]), "=r"(af[mi][1]),
                  "=r"(af[mi][2]), "=r"(af[mi][3])
                : "r"(addr));
        }
#pragma unroll
        for (int ni = 0; ni < 4; ni++) {
            unsigned int bf0, bf1;
            unsigned int baddr = bsmb
                + (unsigned int)((wn * 32 + ni * 8 + brow) * 144)
                + ks * 32 + bhalf * 16;
            asm volatile(
                "ldmatrix.sync.aligned.m8n8.x2.shared.b16 {%0,%1}, [%2];"
                : "=r"(bf0), "=r"(bf1) : "r"(baddr));
#pragma unroll
            for (int mi = 0; mi < 2; mi++) {
                asm volatile(
                    "mma.sync.aligned.m16n8k16.row.col.f32.bf16.bf16.f32 "
                    "{%0,%1,%2,%3}, {%4,%5,%6,%7}, {%8,%9}, {%0,%1,%2,%3};"
                    : "+f"(acc[mi][ni][0]), "+f"(acc[mi][ni][1]),
                      "+f"(acc[mi][ni][2]), "+f"(acc[mi][ni][3])
                    : "r"(af[mi][0]), "r"(af[mi][1]),
                      "r"(af[mi][2]), "r"(af[mi][3]),
                      "r"(bf0), "r"(bf1));
            }
        }
    }

    // ---- epilogue: +bias/4, convert bf16, store ----
    const int slotBase = (g << 12) + (mblk << 7) + wm * 32 + (lane >> 2);
    const int colBase  = (nblk << 6) + wn * 32 + (lane & 3) * 2;
#pragma unroll
    for (int ni = 0; ni < 4; ni++) {
        const int col = colBase + ni * 8;
        const float b0 = 0.25f * __ldg(keyb + col);
        const float b1 = 0.25f * __ldg(keyb + col + 1);
#pragma unroll
        for (int mi = 0; mi < 2; mi++) {
            __nv_bfloat162 lo = __float22bfloat162_rn(
                make_float2(acc[mi][ni][0] + b0, acc[mi][ni][1] + b1));
            __nv_bfloat162 hi = __float22bfloat162_rn(
                make_float2(acc[mi][ni][2] + b0, acc[mi][ni][3] + b1));
            *(unsigned int*)(g_Ktab + (size_t)(slotBase + mi * 16) * 512 + col)
                = *(unsigned int*)&lo;
            *(unsigned int*)(g_Ktab + (size_t)(slotBase + mi * 16 + 8) * 512 + col)
                = *(unsigned int*)&hi;
        }
    }
}

// ---------------------------------------------------------------------------
// Stage 2 main kernel (unchanged R10). Block = 128 threads = 4 stream-warps
// of one 16-token chunk. Prefetched Tok(t+1) issued before compute(t).
// ---------------------------------------------------------------------------
struct Tok {
    uint2  K0, K1, K2, K3;
    float4 v0, v1, v2, v3;
    float4 q;
};

__device__ __forceinline__ float4 bf4(uint2 u) {
    float2 a = __bfloat1622float2(*reinterpret_cast<const __nv_bfloat162*>(&u.x));
    float2 b = __bfloat1622float2(*reinterpret_cast<const __nv_bfloat162*>(&u.y));
    return make_float4(a.x, a.y, b.x, b.y);
}

__global__ void __launch_bounds__(128, 5) engram_main_kernel(
    const float* __restrict__ x,        // (B,T,4,128)
    const int*   __restrict__ ids,      // (B,T)
    const int*   __restrict__ mult,     // (2,2,3)
    const float* __restrict__ wq,       // (4,128)
    const float* __restrict__ wk,       // (4,128)
    const float* __restrict__ convw,    // (512,4)
    const float* __restrict__ convn,    // (4,128)
    float*       __restrict__ out)      // (B,T,4,128)
{
    const int stream = threadIdx.x >> 5;
    const int lane   = threadIdx.x & 31;
    const int b      = blockIdx.x >> 8;
    const int chunk  = blockIdx.x & 255;
    const int t0     = chunk * R_TOK;

    const int c = stream * 128 + lane * 4;
    const int d = lane * 4;

    const float4 wq4  = *(const float4*)(wq + c);
    const float4 wk4  = *(const float4*)(wk + c);
    const float4 wqk4 = make_float4(wq4.x * wk4.x, wq4.y * wk4.y,
                                    wq4.z * wk4.z, wq4.w * wk4.w);
    const float4 cvn4 = *(const float4*)(convn + c);
    const float4 cwA  = *(const float4*)(convw + (c + 0) * 4);
    const float4 cwB  = *(const float4*)(convw + (c + 1) * 4);
    const float4 cwC  = *(const float4*)(convw + (c + 2) * 4);
    const float4 cwD  = *(const float4*)(convw + (c + 3) * 4);

    const int m00 = mult[0],  m01 = mult[1];
    const int m10 = mult[3],  m11 = mult[4];
    const int m20 = mult[6],  m21 = mult[7],  m22 = mult[8];
    const int m30 = mult[9],  m31 = mult[10], m32 = mult[11];

    const float inv128     = 0.0078125f;
    const float eps        = 1.1920929e-7f;
    const float invsqrt128 = 0.08838834764831845f;

    const int    idBase = b * Tq;
    const float* xBase  = x   + (size_t)idBase * CHq + c;
    float*       oBase  = out + (size_t)idBase * CHq + c;

    float4 h1 = make_float4(0.f, 0.f, 0.f, 0.f);
    float4 h2 = h1;
    float4 h3 = h1;

    auto gather = [&](Tok& T, int ia, int ib, int ic, int t) {
        const int h0i = (((ib * m00) ^ (ic * m01)) & 4095);
        const int h1i = (((ib * m10) ^ (ic * m11)) & 4095) + 4096;
        const int h2i = (((ia * m20) ^ (ib * m21) ^ (ic * m22)) & 4095) + 8192;
        const int h3i = (((ia * m30) ^ (ib * m31) ^ (ic * m32)) & 4095) + 12288;
        T.K0 = __ldg((const uint2*)(g_Ktab + (size_t)h0i * 512 + c));
        T.K1 = __ldg((const uint2*)(g_Ktab + (size_t)h1i * 512 + c));
        T.K2 = __ldg((const uint2*)(g_Ktab + (size_t)h2i * 512 + c));
        T.K3 = __ldg((const uint2*)(g_Ktab + (size_t)h3i * 512 + c));
        T.v0 = __ldg((const float4*)(g_Vtab + (size_t)h0i * 128 + d));
        T.v1 = __ldg((const float4*)(g_Vtab + (size_t)h1i * 128 + d));
        T.v2 = __ldg((const float4*)(g_Vtab + (size_t)h2i * 128 + d));
        T.v3 = __ldg((const float4*)(g_Vtab + (size_t)h3i * 128 + d));
        T.q  = *(const float4*)(xBase + (size_t)t * CHq);
    };

    auto compute = [&](const Tok& T, int t, bool store) {
        const float4 k0 = bf4(T.K0);
        const float4 k1 = bf4(T.K1);
        const float4 k2 = bf4(T.K2);
        const float4 k3 = bf4(T.K3);
        float4 kr, vb;
        kr.x = (k0.x + k1.x) + (k2.x + k3.x);
        kr.y = (k0.y + k1.y) + (k2.y + k3.y);
        kr.z = (k0.z + k1.z) + (k2.z + k3.z);
        kr.w = (k0.w + k1.w) + (k2.w + k3.w);
        vb.x = (T.v0.x + T.v1.x) + (T.v2.x + T.v3.x);
        vb.y = (T.v0.y + T.v1.y) + (T.v2.y + T.v3.y);
        vb.z = (T.v0.z + T.v1.z) + (T.v2.z + T.v3.z);
        vb.w = (T.v0.w + T.v1.w) + (T.v2.w + T.v3.w);

        float p0 = T.q.x * T.q.x + T.q.y * T.q.y + T.q.z * T.q.z + T.q.w * T.q.w;
        float p1 = kr.x * kr.x + kr.y * kr.y + kr.z * kr.z + kr.w * kr.w;
        float p2 = T.q.x * kr.x * wqk4.x + T.q.y * kr.y * wqk4.y
                 + T.q.z * kr.z * wqk4.z + T.q.w * kr.w * wqk4.w;
        float p3 = vb.x * vb.x + vb.y * vb.y + vb.z * vb.z + vb.w * vb.w;

        const bool lo = (lane < 16);
        float ea = __shfl_xor_sync(0xffffffffu, p0, 16);
        float eb = __shfl_xor_sync(0xffffffffu, p2, 16);
        float aa = lo ? (p0 + ea) : (p2 + eb);
        float ec = __shfl_xor_sync(0xffffffffu, p1, 16);
        float ed = __shfl_xor_sync(0xffffffffu, p3, 16);
        float bb = lo ? (p1 + ec) : (p3 + ed);
#pragma unroll
        for (int off = 8; off; off >>= 1) {
            aa += __shfl_xor_sync(0xffffffffu, aa, off);
            bb += __shfl_xor_sync(0xffffffffu, bb, off);
        }
        const float a2 = __shfl_xor_sync(0xffffffffu, aa, 16);
        const float b2 = __shfl_xor_sync(0xffffffffu, bb, 16);
        const float sq  = lo ? aa : a2;
        const float sk  = lo ? bb : b2;
        const float sqk = lo ? a2 : aa;
        const float svb = lo ? b2 : bb;

        const float rsq   = rsqrtf(sq * inv128 + eps);
        const float rsk   = rsqrtf(sk * inv128 + eps);
        const float score = sqk * rsq * rsk * invsqrt128;
        const float gate  = __fdividef(1.f, 1.f + __expf(-score));
        const float rr    = rsqrtf(gate * gate * svb * inv128 + eps) * gate;

        float4 xn;
        xn.x = vb.x * rr * cvn4.x;  xn.y = vb.y * rr * cvn4.y;
        xn.z = vb.z * rr * cvn4.z;  xn.w = vb.w * rr * cvn4.w;

        if (store) {
            float4 y;
            y.x = cwA.x * h3.x + cwA.y * h2.x + cwA.z * h1.x + cwA.w * xn.x;
            y.y = cwB.x * h3.y + cwB.y * h2.y + cwB.z * h1.y + cwB.w * xn.y;
            y.z = cwC.x * h3.z + cwC.y * h2.z + cwC.z * h1.z + cwC.w * xn.z;
            y.w = cwD.x * h3.w + cwD.y * h2.w + cwD.z * h1.w + cwD.w * xn.w;
            y.x = __fdividef(y.x, 1.f + __expf(-y.x));
            y.y = __fdividef(y.y, 1.f + __expf(-y.y));
            y.z = __fdividef(y.z, 1.f + __expf(-y.z));
            y.w = __fdividef(y.w, 1.f + __expf(-y.w));
            float4 o;
            o.x = vb.x * gate + y.x;  o.y = vb.y * gate + y.y;
            o.z = vb.z * gate + y.z;  o.w = vb.w * gate + y.w;
            *(float4*)(oBase + (size_t)t * CHq) = o;
        }
        h3 = h2; h2 = h1; h1 = xn;
    };

    int ia = (t0 - 5 >= 0) ? __ldg(ids + idBase + t0 - 5) : 0;
    int ib = (t0 - 4 >= 0) ? __ldg(ids + idBase + t0 - 4) : 0;

#pragma unroll
    for (int tt = -3; tt < 0; tt++) {
        const int t  = t0 + tt;
        const int ic = (t >= 0) ? __ldg(ids + idBase + t) : 0;
        if (t >= 0) {
            Tok P;
            gather(P, ia, ib, ic, t);
            compute(P, t, false);
        }
        ia = ib; ib = ic;
    }

    int ic = __ldg(ids + idBase + t0);
    Tok cur;
    gather(cur, ia, ib, ic, t0);

    for (int tt = 0; tt < R_TOK; tt++) {
        const int t = t0 + tt;
        Tok nxt;
        int in_ = ic;
        if (tt + 1 < R_TOK) {
            in_ = __ldg(ids + idBase + t + 1);
            gather(nxt, ib, ic, in_, t + 1);
        }
        compute(cur, t, true);
        ia = ib; ib = ic; ic = in_;
        cur = nxt;
    }
}

// ---------------------------------------------------------------------------
extern "C" void kernel_launch(void* const* d_in, const int* in_sizes, int n_in,
                              void* d_out, int out_size)
{
    const float* x          = (const float*)d_in[0];
    const int*   input_ids  = (const int*)  d_in[1];
    const int*   multipliers= (const int*)  d_in[2];
    const float* embedding  = (const float*)d_in[3];
    const float* val_W      = (const float*)d_in[4];
    const float* val_b      = (const float*)d_in[5];
    const float* key_W      = (const float*)d_in[6];
    const float* key_b      = (const float*)d_in[7];
    const float* normq_w    = (const float*)d_in[8];
    const float* normk_w    = (const float*)d_in[9];
    const float* conv_w     = (const float*)d_in[10];
    const float* convnorm_w = (const float*)d_in[11];
    float* out = (float*)d_out;

    precompute_v_kernel<<<dim3(2, 32, 4), 128>>>(embedding, val_W, val_b);
    ktab_mma_kernel<<<dim3(8, 32, 4), 256>>>(embedding, key_W, key_b);

    engram_main_kernel<<<Bq * CHUNKS, 128>>>(
        x, input_ids, multipliers,
        normq_w, normk_w, conv_w, convnorm_w, out);
}